// round 16
// baseline (speedup 1.0000x reference)
#include <cuda_runtime.h>
#include <cuda_fp16.h>
#include <stdint.h>

#define BB 2
#define SEQ 2048
#define DIM 1024
#define NH 16
#define DH 64
#define NBH (BB * NH)     // 32
#define BS  (BB * SEQ)    // 4096

// ---- fp16 scratch ----
__device__ __half g_xh[(size_t)BS * DIM];           // x hi
__device__ __half g_xl[(size_t)BS * DIM];           // x lo
__device__ __half g_wt[(size_t)4 * DIM * DIM];      // W^T fp16-hi: [z][n][k]
__device__ __half g_qh[(size_t)NBH * SEQ * DH];     // Q hi [bh][s][dh]
__device__ __half g_ql[(size_t)NBH * SEQ * DH];     // Q lo
__device__ __half g_kh[(size_t)NBH * SEQ * DH];     // K hi
__device__ __half g_vn[(size_t)NBH * SEQ * DH];     // V hi [bh][s][dh]
__device__ __half g_vT[(size_t)NBH * DH * SEQ];     // V^T hi [bh][dh][s]
__device__ __half g_ch[(size_t)BS * DIM];           // ctx hi [B*S][D]
__device__ __half g_cl[(size_t)BS * DIM];           // ctx lo
__device__ __half g_pt[(size_t)NBH * SEQ * SEQ];    // P~ = exp(s - m_tile), fp16
__device__ __half g_mk[(size_t)SEQ * SEQ];          // fp16(mask * -1e9)
__device__ float  g_pm[(size_t)NBH * SEQ * 32];     // per-tile max m_t
__device__ float  g_rowC[(size_t)NBH * SEQ];        // per-row C = m + lnZ

// ============================ low-level helpers ============================
__device__ __forceinline__ uint32_t sptr(const void* p) {
    return (uint32_t)__cvta_generic_to_shared(p);
}
__device__ __forceinline__ void cp16(uint32_t dst, const void* src) {
    asm volatile("cp.async.cg.shared.global [%0], [%1], 16;" :: "r"(dst), "l"(src));
}
__device__ __forceinline__ void cp_commit() { asm volatile("cp.async.commit_group;"); }
__device__ __forceinline__ void cp_wait1()  { asm volatile("cp.async.wait_group 1;"); }
__device__ __forceinline__ void cp_wait0()  { asm volatile("cp.async.wait_group 0;"); }

__device__ __forceinline__ void ldm_x4(uint32_t* r, uint32_t addr) {
    asm volatile("ldmatrix.sync.aligned.m8n8.x4.shared.b16 {%0,%1,%2,%3}, [%4];"
                 : "=r"(r[0]), "=r"(r[1]), "=r"(r[2]), "=r"(r[3]) : "r"(addr));
}
__device__ __forceinline__ void mma16816(float* d, const uint32_t* a,
                                         const uint32_t* b) {
    asm volatile(
        "mma.sync.aligned.m16n8k16.row.col.f32.f16.f16.f32 "
        "{%0,%1,%2,%3}, {%4,%5,%6,%7}, {%8,%9}, {%0,%1,%2,%3};"
        : "+f"(d[0]), "+f"(d[1]), "+f"(d[2]), "+f"(d[3])
        : "r"(a[0]), "r"(a[1]), "r"(a[2]), "r"(a[3]), "r"(b[0]), "r"(b[1]));
}
__device__ __forceinline__ uint32_t pack_split(float x) {
    __half h = __float2half(x);
    float hf = __half2float(h);
    __half l = __float2half(x - hf);
    return (uint32_t)__half_as_ushort(h) | ((uint32_t)__half_as_ushort(l) << 16);
}
__device__ __forceinline__ void stcs4(float* p, float4 v) {
    asm volatile("st.global.cs.v4.f32 [%0], {%1,%2,%3,%4};"
                 :: "l"(p), "f"(v.x), "f"(v.y), "f"(v.z), "f"(v.w) : "memory");
}

// ============================ warp-MMA block (proj/out) ============================
// Pipelined issue order: 4 independent hi-MMAs, then 4 lo-MMAs — the two
// updates of each accumulator are separated by 3 ops (covers HMMA latency).
// Per-accumulator order stays hi-then-lo: bit-identical accumulation.
template <int STRIDE, int KSTEPS, int NT>
__device__ __forceinline__ void mma_block(const char* Ah, const char* Al,
                                          const char* Bh,
                                          int wm, int wn, int lane,
                                          float (&acc)[2][NT][4]) {
    uint32_t ahb = sptr(Ah), alb = sptr(Al), bhb = sptr(Bh);
#pragma unroll
    for (int ks = 0; ks < KSTEPS; ks++) {
        uint32_t ah[2][4], al[2][4];
#pragma unroll
        for (int mt = 0; mt < 2; mt++) {
            uint32_t off = (uint32_t)(32 * wm + 16 * mt + (lane & 15)) * STRIDE +
                           ((lane >> 4) * 16) + ks * 32;
            ldm_x4(ah[mt], ahb + off);
            ldm_x4(al[mt], alb + off);
        }
#pragma unroll
        for (int np = 0; np < NT / 2; np++) {
            uint32_t boff = (uint32_t)(NT * 8 * wn + np * 16 +
                                       ((lane >> 4) << 3) + (lane & 7)) * STRIDE +
                            (((lane >> 3) & 1) * 16) + ks * 32;
            uint32_t bh[4];
            ldm_x4(bh, bhb + boff);
            // hi wave (independent)
            mma16816(acc[0][2 * np],     ah[0], bh);
            mma16816(acc[1][2 * np],     ah[1], bh);
            mma16816(acc[0][2 * np + 1], ah[0], bh + 2);
            mma16816(acc[1][2 * np + 1], ah[1], bh + 2);
            // lo wave
            mma16816(acc[0][2 * np],     al[0], bh);
            mma16816(acc[1][2 * np],     al[1], bh);
            mma16816(acc[0][2 * np + 1], al[0], bh + 2);
            mma16816(acc[1][2 * np + 1], al[1], bh + 2);
        }
    }
}

// ============================ prep kernels ============================
__global__ void split_x(const float* __restrict__ x) {
    size_t i = ((size_t)blockIdx.x * blockDim.x + threadIdx.x) * 4;
    float4 f = *(const float4*)(x + i);
    uint32_t p0 = pack_split(f.x), p1 = pack_split(f.y);
    uint32_t p2 = pack_split(f.z), p3 = pack_split(f.w);
    uint2 h, l;
    h.x = (p0 & 0xffffu) | (p1 << 16);
    h.y = (p2 & 0xffffu) | (p3 << 16);
    l.x = (p0 >> 16) | (p1 & 0xffff0000u);
    l.y = (p2 >> 16) | (p3 & 0xffff0000u);
    *(uint2*)(g_xh + i) = h;
    *(uint2*)(g_xl + i) = l;
}

// g_mk = fp16(mask * -1e9)
__global__ void pack_mask(const float* __restrict__ mask) {
    size_t i = ((size_t)blockIdx.x * blockDim.x + threadIdx.x) * 4;
    float4 f = *(const float4*)(mask + i);
    uint2 o;
    __half2 h0 = __floats2half2_rn(f.x * (-1e9f), f.y * (-1e9f));
    __half2 h1 = __floats2half2_rn(f.z * (-1e9f), f.w * (-1e9f));
    o.x = *(uint32_t*)&h0;
    o.y = *(uint32_t*)&h1;
    *(uint2*)(g_mk + i) = o;
}

__global__ void transpose_pack_w(const float* __restrict__ Wq,
                                 const float* __restrict__ Wk,
                                 const float* __restrict__ Wv,
                                 const float* __restrict__ Wo) {
    __shared__ __half t[32][33];
    int z = blockIdx.z;
    const float* W = (z == 0) ? Wq : (z == 1) ? Wk : (z == 2) ? Wv : Wo;
    __half* dst = g_wt + (size_t)z * DIM * DIM;
    int n0 = blockIdx.x * 32, k0 = blockIdx.y * 32;
    int tx = threadIdx.x, ty = threadIdx.y;    // 32 x 8
#pragma unroll
    for (int r = 0; r < 4; r++) {
        int k = k0 + ty + r * 8;
        t[ty + r * 8][tx] = __float2half(W[(size_t)k * DIM + n0 + tx]);
    }
    __syncthreads();
#pragma unroll
    for (int r = 0; r < 4; r++) {
        int n = n0 + ty + r * 8;
        dst[(size_t)n * DIM + k0 + tx] = t[tx][ty + r * 8];
    }
}

__global__ void transpose_v() {
    __shared__ __half t[32][33];
    int bh = blockIdx.z;
    int s0 = blockIdx.x * 32, d0 = blockIdx.y * 32;
    int tx = threadIdx.x, ty = threadIdx.y;    // 32 x 8
    const __half* src = g_vn + (size_t)bh * SEQ * DH;
    __half* dst = g_vT + (size_t)bh * DH * SEQ;
#pragma unroll
    for (int r = 0; r < 4; r++) {
        int s = s0 + ty + r * 8;
        t[ty + r * 8][tx] = src[(size_t)s * DH + d0 + tx];
    }
    __syncthreads();
#pragma unroll
    for (int r = 0; r < 4; r++) {
        int d = d0 + ty + r * 8;
        dst[(size_t)d * SEQ + s0 + tx] = t[tx][ty + r * 8];
    }
}

// ============================ GEMM body (proj & out): cp.async 3-stage ============================
#define P_ST 80
#define P_ARR 10240
#define P_BUF (3 * P_ARR)

template <typename EPI>
__device__ __forceinline__ void gemm128_body(const __half* Xh, const __half* Xl,
                                             const __half* Bt, char* sm, EPI epi) {
    const int tid = threadIdx.x, lane = tid & 31, wid = tid >> 5;
    const int wm = wid >> 1, wn = wid & 1;
    float acc[2][8][4] = {};

    const int r0 = tid >> 2, c0 = (tid & 3) * 16;
    const int r1 = (tid + 256) >> 2, c1 = ((tid + 256) & 3) * 16;

    auto issue = [&](int c) {
        char* base = sm + (c % 3) * P_BUF;
        uint32_t Ah = sptr(base), Al = Ah + P_ARR, Bh = Al + P_ARR;
        int k0 = c * 32;
        cp16(Ah + r0 * P_ST + c0, Xh + (size_t)r0 * DIM + k0 + c0 / 2);
        cp16(Ah + r1 * P_ST + c1, Xh + (size_t)r1 * DIM + k0 + c1 / 2);
        cp16(Al + r0 * P_ST + c0, Xl + (size_t)r0 * DIM + k0 + c0 / 2);
        cp16(Al + r1 * P_ST + c1, Xl + (size_t)r1 * DIM + k0 + c1 / 2);
        cp16(Bh + r0 * P_ST + c0, Bt + (size_t)r0 * DIM + k0 + c0 / 2);
        cp16(Bh + r1 * P_ST + c1, Bt + (size_t)r1 * DIM + k0 + c1 / 2);
        cp_commit();
    };
    issue(0); issue(1);
    for (int c = 0; c < 32; c++) {
        if (c < 31) cp_wait1(); else cp_wait0();
        __syncthreads();
        char* base = sm + (c % 3) * P_BUF;
        mma_block<P_ST, 2, 8>(base, base + P_ARR, base + 2 * P_ARR,
                              wm, wn, lane, acc);
        if (c + 2 < 32) issue(c + 2);
    }
    epi(acc, wm, wn, lane);
}

__global__ void __launch_bounds__(256, 2)
proj_mma(const float* __restrict__ bq, const float* __restrict__ bk,
         const float* __restrict__ bv) {
    extern __shared__ char sm[];
    const int z = blockIdx.z;
    const int bn = blockIdx.x * 128, bm = blockIdx.y * 128;
    const __half* Bt = g_wt + (size_t)z * DIM * DIM + (size_t)bn * DIM;
    const float* bias = (z == 0) ? bq : (z == 1) ? bk : bv;

    gemm128_body(g_xh + (size_t)bm * DIM, g_xl + (size_t)bm * DIM, Bt, sm,
        [&](float (&acc)[2][8][4], int wm, int wn, int lane) {
#pragma unroll
            for (int mt = 0; mt < 2; mt++) {
#pragma unroll
                for (int nt = 0; nt < 8; nt++) {
                    int n = bn + 64 * wn + 8 * nt + 2 * (lane & 3);
                    float bx = bias[n], by = bias[n + 1];
                    int h = n >> 6, dh = n & 63;
                    int m0 = bm + 32 * wm + 16 * mt + (lane >> 2);
#pragma unroll
                    for (int half = 0; half < 2; half++) {
                        int m = m0 + 8 * half;
                        int b = m >> 11, s = m & 2047;
                        float va = acc[mt][nt][2 * half + 0] + bx;
                        float vb = acc[mt][nt][2 * half + 1] + by;
                        size_t off = ((size_t)(b * NH + h) * SEQ + s) * DH + dh;
                        __half ha = __float2half(va);
                        __half hb = __float2half(vb);
                        if (z == 0) {
                            __half la = __float2half(va - __half2float(ha));
                            __half lb = __float2half(vb - __half2float(hb));
                            *(__half2*)(g_qh + off) = __halves2half2(ha, hb);
                            *(__half2*)(g_ql + off) = __halves2half2(la, lb);
                        } else if (z == 1) {
                            *(__half2*)(g_kh + off) = __halves2half2(ha, hb);
                        } else {
                            *(__half2*)(g_vn + off) = __halves2half2(ha, hb);
                        }
                    }
                }
            }
        });
}

__global__ void __launch_bounds__(256, 2)
out_mma(const float* __restrict__ bo, float* __restrict__ out) {
    extern __shared__ char sm[];
    const int bn = blockIdx.x * 128, bm = blockIdx.y * 128;
    const __half* Bt = g_wt + (size_t)3 * DIM * DIM + (size_t)bn * DIM;

    gemm128_body(g_ch + (size_t)bm * DIM, g_cl + (size_t)bm * DIM, Bt, sm,
        [&](float (&acc)[2][8][4], int wm, int wn, int lane) {
#pragma unroll
            for (int mt = 0; mt < 2; mt++) {
#pragma unroll
                for (int nt = 0; nt < 8; nt++) {
                    int n = bn + 64 * wn + 8 * nt + 2 * (lane & 3);
                    float bx = bo[n], by = bo[n + 1];
                    int m0 = bm + 32 * wm + 16 * mt + (lane >> 2);
#pragma unroll
                    for (int half = 0; half < 2; half++) {
                        int m = m0 + 8 * half;
                        float2 o;
                        o.x = acc[mt][nt][2 * half + 0] + bx;
                        o.y = acc[mt][nt][2 * half + 1] + by;
                        *(float2*)(out + (size_t)m * DIM + n) = o;
                    }
                }
            }
        });
}

// ============================ flash (FA-2, pipelined MMA issue) ============================
#define F_ST 144
#define F_ARR 9216            // 64 x 144
#define F_SMEM (6 * F_ARR)    // 55296

__global__ void __launch_bounds__(128, 4)
flash_mma() {
    extern __shared__ char sm[];
    const int tid = threadIdx.x, lane = tid & 31, wid = tid >> 5;
    const int tid2 = lane & 3;
    const int bh = blockIdx.y;
    const int b = bh >> 4, h = bh & 15;
    const int qt = blockIdx.x * 64;
    const uint32_t sb = sptr(sm);
    const int row0 = wid * 16 + (lane >> 2);   // local q-row
    const int row1 = row0 + 8;

    auto issueKV = [&](int t) {
        int buf = t & 1;
        int kt = t * 64;
#pragma unroll
        for (int it = 0; it < 4; it++) {
            int idx = it * 128 + tid;
            int row = idx >> 3, c = idx & 7;
            cp16(sb + 2 * F_ARR + buf * F_ARR + row * F_ST + c * 16,
                 g_kh + ((size_t)bh * SEQ + kt + row) * DH + c * 8);
            cp16(sb + 4 * F_ARR + buf * F_ARR + row * F_ST + c * 16,
                 g_vT + ((size_t)bh * DH + row) * SEQ + kt + c * 8);
        }
        cp_commit();
    };
    {
#pragma unroll
        for (int it = 0; it < 4; it++) {
            int idx = it * 128 + tid;
            int row = idx >> 3, c = idx & 7;
            size_t src = ((size_t)bh * SEQ + qt + row) * DH + c * 8;
            cp16(sb + row * F_ST + c * 16, g_qh + src);
            cp16(sb + F_ARR + row * F_ST + c * 16, g_ql + src);
        }
        issueKV(0);
        issueKV(1);
    }

    float M0 = -1e30f, M1 = -1e30f, Z0 = 0.f, Z1 = 0.f;
    float acc_c[8][4] = {};

    for (int t = 0; t < 32; t++) {
        const int kt = t * 64;
        const int buf = t & 1;
        if (t < 31) cp_wait1(); else cp_wait0();
        __syncthreads();

        // ---- S = Q @ K^T (2-term A split, np-paired pipelined issue) ----
        float acc_s[8][4] = {};
        const uint32_t kbase = sb + 2 * F_ARR + buf * F_ARR;
#pragma unroll
        for (int ks = 0; ks < 4; ks++) {
            uint32_t ah[4], al[4];
            uint32_t aoff = (uint32_t)(wid * 16 + (lane & 15)) * F_ST +
                            ((lane >> 4) * 16) + ks * 32;
            ldm_x4(ah, sb + aoff);
            ldm_x4(al, sb + F_ARR + aoff);
#pragma unroll
            for (int pp = 0; pp < 2; pp++) {
                uint32_t boff0 = (uint32_t)(pp * 32 + ((lane >> 4) << 3) +
                                            (lane & 7)) * F_ST +
                                 (((lane >> 3) & 1) * 16) + ks * 32;
                uint32_t boff1 = boff0 + 16 * F_ST;
                uint32_t b0[4], b1[4];
                ldm_x4(b0, kbase + boff0);
                ldm_x4(b1, kbase + boff1);
                // hi wave
                mma16816(acc_s[4 * pp + 0], ah, b0);
                mma16816(acc_s[4 * pp + 1], ah, b0 + 2);
                mma16816(acc_s[4 * pp + 2], ah, b1);
                mma16816(acc_s[4 * pp + 3], ah, b1 + 2);
                // lo wave
                mma16816(acc_s[4 * pp + 0], al, b0);
                mma16816(acc_s[4 * pp + 1], al, b0 + 2);
                mma16816(acc_s[4 * pp + 2], al, b1);
                mma16816(acc_s[4 * pp + 3], al, b1 + 2);
            }
        }

        // ---- scale + premasked fp16 add + in-quad row max ----
        const float scale = 0.125f;
        float mx0 = -1e30f, mx1 = -1e30f;
        const __half* mr0 = g_mk + (size_t)(qt + row0) * SEQ + kt;
        const __half* mr1 = g_mk + (size_t)(qt + row1) * SEQ + kt;
#pragma unroll
        for (int nt = 0; nt < 8; nt++) {
            int kc = nt * 8 + tid2 * 2;
            float2 mv0 = __half22float2(*(const __half2*)(mr0 + kc));
            float2 mv1 = __half22float2(*(const __half2*)(mr1 + kc));
            acc_s[nt][0] = acc_s[nt][0] * scale + mv0.x;
            acc_s[nt][1] = acc_s[nt][1] * scale + mv0.y;
            acc_s[nt][2] = acc_s[nt][2] * scale + mv1.x;
            acc_s[nt][3] = acc_s[nt][3] * scale + mv1.y;
            mx0 = fmaxf(mx0, fmaxf(acc_s[nt][0], acc_s[nt][1]));
            mx1 = fmaxf(mx1, fmaxf(acc_s[nt][2], acc_s[nt][3]));
        }
        mx0 = fmaxf(mx0, __shfl_xor_sync(0xffffffffu, mx0, 1));
        mx0 = fmaxf(mx0, __shfl_xor_sync(0xffffffffu, mx0, 2));
        mx1 = fmaxf(mx1, __shfl_xor_sync(0xffffffffu, mx1, 1));
        mx1 = fmaxf(mx1, __shfl_xor_sync(0xffffffffu, mx1, 2));

        float Mn0 = fmaxf(M0, mx0), Mn1 = fmaxf(M1, mx1);
        float f0 = __expf(M0 - Mn0), f1 = __expf(M1 - Mn1);
        float g0 = __expf(mx0 - Mn0), g1 = __expf(mx1 - Mn1);
        M0 = Mn0; M1 = Mn1;
        if (tid2 == 0) {
            g_pm[((size_t)bh * SEQ + qt + row0) * 32 + t] = mx0;
            g_pm[((size_t)bh * SEQ + qt + row1) * 32 + t] = mx1;
        }

        // ---- exp, P~ gmem store, in-register A-frags, partial sums ----
        __half* p0 = g_pt + ((size_t)bh * SEQ + qt + row0) * SEQ + kt;
        __half* p1 = g_pt + ((size_t)bh * SEQ + qt + row1) * SEQ + kt;
        uint32_t fa[8], fb[8];
        float s0 = 0.f, s1 = 0.f;
#pragma unroll
        for (int nt = 0; nt < 8; nt++) {
            int kc = nt * 8 + tid2 * 2;
            float e0 = __expf(acc_s[nt][0] - mx0);
            float e1 = __expf(acc_s[nt][1] - mx0);
            float e2 = __expf(acc_s[nt][2] - mx1);
            float e3 = __expf(acc_s[nt][3] - mx1);
            s0 += e0 + e1;
            s1 += e2 + e3;
            *(__half2*)(p0 + kc) = __floats2half2_rn(e0, e1);
            *(__half2*)(p1 + kc) = __floats2half2_rn(e2, e3);
            __half2 a2 = __floats2half2_rn(e0 * g0, e1 * g0);
            __half2 b2 = __floats2half2_rn(e2 * g1, e3 * g1);
            fa[nt] = *(uint32_t*)&a2;
            fb[nt] = *(uint32_t*)&b2;
        }
        s0 += __shfl_xor_sync(0xffffffffu, s0, 1);
        s0 += __shfl_xor_sync(0xffffffffu, s0, 2);
        s1 += __shfl_xor_sync(0xffffffffu, s1, 1);
        s1 += __shfl_xor_sync(0xffffffffu, s1, 2);
        Z0 = Z0 * f0 + s0 * g0;
        Z1 = Z1 * f1 + s1 * g1;

        // ---- rescale running ctx ----
#pragma unroll
        for (int nt = 0; nt < 8; nt++) {
            acc_c[nt][0] *= f0; acc_c[nt][1] *= f0;
            acc_c[nt][2] *= f1; acc_c[nt][3] *= f1;
        }

        // ---- ctx += P @ V^T (A-frags straight from registers) ----
        const uint32_t vbase = sb + 4 * F_ARR + buf * F_ARR;
#pragma unroll
        for (int ks = 0; ks < 4; ks++) {
            uint32_t a[4] = { fa[2 * ks], fb[2 * ks],
                              fa[2 * ks + 1], fb[2 * ks + 1] };
#pragma unroll
            for (int np = 0; np < 4; np++) {
                uint32_t boff = (uint32_t)(np * 16 + ((lane >> 4) << 3) +
                                           (lane & 7)) * F_ST +
                                (((lane >> 3) & 1) * 16) + ks * 32;
                uint32_t bv4[4];
                ldm_x4(bv4, vbase + boff);
                mma16816(acc_c[2 * np],     a, bv4);
                mma16816(acc_c[2 * np + 1], a, bv4 + 2);
            }
        }
        __syncthreads();
        if (t + 2 < 32) issueKV(t + 2);
    }

    // ---- epilogue ----
    if (tid2 == 0) {
        g_rowC[(size_t)bh * SEQ + qt + row0] = M0 + __logf(Z0);
        g_rowC[(size_t)bh * SEQ + qt + row1] = M1 + __logf(Z1);
    }
    float i0 = 1.0f / Z0, i1 = 1.0f / Z1;
    size_t o0 = ((size_t)b * SEQ + qt + row0) * DIM + h * DH;
    size_t o1 = ((size_t)b * SEQ + qt + row1) * DIM + h * DH;
#pragma unroll
    for (int nt = 0; nt < 8; nt++) {
        int nl = nt * 8 + tid2 * 2;
        float va = acc_c[nt][0] * i0, vb = acc_c[nt][1] * i0;
        float vc = acc_c[nt][2] * i1, vd = acc_c[nt][3] * i1;
        __half ha = __float2half(va), hb = __float2half(vb);
        __half hc = __float2half(vc), hd = __float2half(vd);
        *(__half2*)(g_ch + o0 + nl) = __halves2half2(ha, hb);
        *(__half2*)(g_cl + o0 + nl) =
            __halves2half2(__float2half(va - __half2float(ha)),
                           __float2half(vb - __half2float(hb)));
        *(__half2*)(g_ch + o1 + nl) = __halves2half2(hc, hd);
        *(__half2*)(g_cl + o1 + nl) =
            __halves2half2(__float2half(vc - __half2float(hc)),
                           __float2half(vd - __half2float(hd)));
    }
}

// ============================ normalize: attn = P~ * exp(m_t - C) ============================
__global__ void __launch_bounds__(256)
normalize_attn(float* __restrict__ attn) {
    const size_t row = blockIdx.x;           // bh*SEQ + qrow
    const int tid = threadIdx.x;
    const __half* p = g_pt + row * SEQ;
    float* a = attn + row * SEQ;
    const float C = g_rowC[row];
    const int e0 = tid * 8;
    const float sc = __expf(g_pm[row * 32 + (e0 >> 6)] - C);
    uint4 raw = *(const uint4*)(p + e0);
    const __half2* hp = (const __half2*)&raw;
    float2 f0 = __half22float2(hp[0]);
    float2 f1 = __half22float2(hp[1]);
    float2 f2 = __half22float2(hp[2]);
    float2 f3 = __half22float2(hp[3]);
    stcs4(a + e0,     make_float4(f0.x * sc, f0.y * sc, f1.x * sc, f1.y * sc));
    stcs4(a + e0 + 4, make_float4(f2.x * sc, f2.y * sc, f3.x * sc, f3.y * sc));
}

// ============================ launcher ============================
extern "C" void kernel_launch(void* const* d_in, const int* in_sizes, int n_in,
                              void* d_out, int out_size) {
    const float* x    = (const float*)d_in[0];
    const float* mask = (const float*)d_in[1];
    const float* Wq   = (const float*)d_in[2];
    const float* bq   = (const float*)d_in[3];
    const float* Wk   = (const float*)d_in[4];
    const float* bk   = (const float*)d_in[5];
    const float* Wv   = (const float*)d_in[6];
    const float* bv   = (const float*)d_in[7];
    const float* Wo   = (const float*)d_in[8];
    const float* bo   = (const float*)d_in[9];

    float* out  = (float*)d_out;                 // [B,S,D]
    float* attn = out + (size_t)BS * DIM;        // [B,H,S,S]

    const int projSmem = 3 * P_BUF;              // 92160
    cudaFuncSetAttribute(proj_mma,  cudaFuncAttributeMaxDynamicSharedMemorySize, projSmem);
    cudaFuncSetAttribute(flash_mma, cudaFuncAttributeMaxDynamicSharedMemorySize, F_SMEM);
    cudaFuncSetAttribute(out_mma,   cudaFuncAttributeMaxDynamicSharedMemorySize, projSmem);

    split_x<<<BS * DIM / 1024, 256>>>(x);
    pack_mask<<<(size_t)SEQ * SEQ / 1024, 256>>>(mask);
    transpose_pack_w<<<dim3(32, 32, 4), dim3(32, 8)>>>(Wq, Wk, Wv, Wo);
    proj_mma<<<dim3(8, 32, 3), 256, projSmem>>>(bq, bk, bv);
    transpose_v<<<dim3(64, 2, 32), dim3(32, 8)>>>();
    flash_mma<<<dim3(32, 32), 128, F_SMEM>>>();
    normalize_attn<<<NBH * SEQ, 256>>>(attn);
    out_mma<<<dim3(8, 32), 256, projSmem>>>(bo, out);
}

// round 17
// speedup vs baseline: 1.0259x; 1.0259x over previous
#include <cuda_runtime.h>
#include <cuda_fp16.h>
#include <stdint.h>

#define BB 2
#define SEQ 2048
#define DIM 1024
#define NH 16
#define DH 64
#define NBH (BB * NH)     // 32
#define BS  (BB * SEQ)    // 4096

// ---- fp16 scratch ----
__device__ __half g_xh[(size_t)BS * DIM];           // x hi
__device__ __half g_xl[(size_t)BS * DIM];           // x lo
__device__ __half g_wt[(size_t)4 * DIM * DIM];      // W^T fp16-hi: [z][n][k]
__device__ __half g_qh[(size_t)NBH * SEQ * DH];     // Q hi [bh][s][dh]
__device__ __half g_ql[(size_t)NBH * SEQ * DH];     // Q lo
__device__ __half g_kh[(size_t)NBH * SEQ * DH];     // K hi
__device__ __half g_vn[(size_t)NBH * SEQ * DH];     // V hi [bh][s][dh]
__device__ __half g_vT[(size_t)NBH * DH * SEQ];     // V^T hi [bh][dh][s]
__device__ __half g_ch[(size_t)BS * DIM];           // ctx hi [B*S][D]
__device__ __half g_cl[(size_t)BS * DIM];           // ctx lo
__device__ __half g_pt[(size_t)NBH * SEQ * SEQ];    // P~ = exp(s - m_tile), fp16
__device__ __half g_mk[(size_t)SEQ * SEQ];          // fp16(mask * -1e9)
__device__ float  g_pm[(size_t)NBH * SEQ * 32];     // per-tile max m_t
__device__ float  g_rowC[(size_t)NBH * SEQ];        // per-row C = m + lnZ

// ============================ low-level helpers ============================
__device__ __forceinline__ uint32_t sptr(const void* p) {
    return (uint32_t)__cvta_generic_to_shared(p);
}
__device__ __forceinline__ void cp16(uint32_t dst, const void* src) {
    asm volatile("cp.async.cg.shared.global [%0], [%1], 16;" :: "r"(dst), "l"(src));
}
__device__ __forceinline__ void cp_commit() { asm volatile("cp.async.commit_group;"); }
__device__ __forceinline__ void cp_wait1()  { asm volatile("cp.async.wait_group 1;"); }
__device__ __forceinline__ void cp_wait0()  { asm volatile("cp.async.wait_group 0;"); }

__device__ __forceinline__ void ldm_x4(uint32_t* r, uint32_t addr) {
    asm volatile("ldmatrix.sync.aligned.m8n8.x4.shared.b16 {%0,%1,%2,%3}, [%4];"
                 : "=r"(r[0]), "=r"(r[1]), "=r"(r[2]), "=r"(r[3]) : "r"(addr));
}
__device__ __forceinline__ void mma16816(float* d, const uint32_t* a,
                                         const uint32_t* b) {
    asm volatile(
        "mma.sync.aligned.m16n8k16.row.col.f32.f16.f16.f32 "
        "{%0,%1,%2,%3}, {%4,%5,%6,%7}, {%8,%9}, {%0,%1,%2,%3};"
        : "+f"(d[0]), "+f"(d[1]), "+f"(d[2]), "+f"(d[3])
        : "r"(a[0]), "r"(a[1]), "r"(a[2]), "r"(a[3]), "r"(b[0]), "r"(b[1]));
}
__device__ __forceinline__ uint32_t pack_split(float x) {
    __half h = __float2half(x);
    float hf = __half2float(h);
    __half l = __float2half(x - hf);
    return (uint32_t)__half_as_ushort(h) | ((uint32_t)__half_as_ushort(l) << 16);
}
__device__ __forceinline__ void stcs4(float* p, float4 v) {
    asm volatile("st.global.cs.v4.f32 [%0], {%1,%2,%3,%4};"
                 :: "l"(p), "f"(v.x), "f"(v.y), "f"(v.z), "f"(v.w) : "memory");
}

// ============================ warp-MMA block (proj/out, R15 order) ============================
template <int STRIDE, int KSTEPS, int NT>
__device__ __forceinline__ void mma_block(const char* Ah, const char* Al,
                                          const char* Bh,
                                          int wm, int wn, int lane,
                                          float (&acc)[2][NT][4]) {
    uint32_t ahb = sptr(Ah), alb = sptr(Al), bhb = sptr(Bh);
#pragma unroll
    for (int ks = 0; ks < KSTEPS; ks++) {
        uint32_t ah[2][4], al[2][4];
#pragma unroll
        for (int mt = 0; mt < 2; mt++) {
            uint32_t off = (uint32_t)(32 * wm + 16 * mt + (lane & 15)) * STRIDE +
                           ((lane >> 4) * 16) + ks * 32;
            ldm_x4(ah[mt], ahb + off);
            ldm_x4(al[mt], alb + off);
        }
#pragma unroll
        for (int np = 0; np < NT / 2; np++) {
            uint32_t boff = (uint32_t)(NT * 8 * wn + np * 16 +
                                       ((lane >> 4) << 3) + (lane & 7)) * STRIDE +
                            (((lane >> 3) & 1) * 16) + ks * 32;
            uint32_t bh[4];
            ldm_x4(bh, bhb + boff);
#pragma unroll
            for (int mt = 0; mt < 2; mt++) {
                mma16816(acc[mt][2 * np],     ah[mt], bh);
                mma16816(acc[mt][2 * np],     al[mt], bh);
                mma16816(acc[mt][2 * np + 1], ah[mt], bh + 2);
                mma16816(acc[mt][2 * np + 1], al[mt], bh + 2);
            }
        }
    }
}

// ============================ prep kernels ============================
__global__ void split_x(const float* __restrict__ x) {
    size_t i = ((size_t)blockIdx.x * blockDim.x + threadIdx.x) * 4;
    float4 f = *(const float4*)(x + i);
    uint32_t p0 = pack_split(f.x), p1 = pack_split(f.y);
    uint32_t p2 = pack_split(f.z), p3 = pack_split(f.w);
    uint2 h, l;
    h.x = (p0 & 0xffffu) | (p1 << 16);
    h.y = (p2 & 0xffffu) | (p3 << 16);
    l.x = (p0 >> 16) | (p1 & 0xffff0000u);
    l.y = (p2 >> 16) | (p3 & 0xffff0000u);
    *(uint2*)(g_xh + i) = h;
    *(uint2*)(g_xl + i) = l;
}

// g_mk = fp16(mask * -1e9)
__global__ void pack_mask(const float* __restrict__ mask) {
    size_t i = ((size_t)blockIdx.x * blockDim.x + threadIdx.x) * 4;
    float4 f = *(const float4*)(mask + i);
    uint2 o;
    __half2 h0 = __floats2half2_rn(f.x * (-1e9f), f.y * (-1e9f));
    __half2 h1 = __floats2half2_rn(f.z * (-1e9f), f.w * (-1e9f));
    o.x = *(uint32_t*)&h0;
    o.y = *(uint32_t*)&h1;
    *(uint2*)(g_mk + i) = o;
}

__global__ void transpose_pack_w(const float* __restrict__ Wq,
                                 const float* __restrict__ Wk,
                                 const float* __restrict__ Wv,
                                 const float* __restrict__ Wo) {
    __shared__ __half t[32][33];
    int z = blockIdx.z;
    const float* W = (z == 0) ? Wq : (z == 1) ? Wk : (z == 2) ? Wv : Wo;
    __half* dst = g_wt + (size_t)z * DIM * DIM;
    int n0 = blockIdx.x * 32, k0 = blockIdx.y * 32;
    int tx = threadIdx.x, ty = threadIdx.y;    // 32 x 8
#pragma unroll
    for (int r = 0; r < 4; r++) {
        int k = k0 + ty + r * 8;
        t[ty + r * 8][tx] = __float2half(W[(size_t)k * DIM + n0 + tx]);
    }
    __syncthreads();
#pragma unroll
    for (int r = 0; r < 4; r++) {
        int n = n0 + ty + r * 8;
        dst[(size_t)n * DIM + k0 + tx] = t[tx][ty + r * 8];
    }
}

__global__ void transpose_v() {
    __shared__ __half t[32][33];
    int bh = blockIdx.z;
    int s0 = blockIdx.x * 32, d0 = blockIdx.y * 32;
    int tx = threadIdx.x, ty = threadIdx.y;    // 32 x 8
    const __half* src = g_vn + (size_t)bh * SEQ * DH;
    __half* dst = g_vT + (size_t)bh * DH * SEQ;
#pragma unroll
    for (int r = 0; r < 4; r++) {
        int s = s0 + ty + r * 8;
        t[ty + r * 8][tx] = src[(size_t)s * DH + d0 + tx];
    }
    __syncthreads();
#pragma unroll
    for (int r = 0; r < 4; r++) {
        int d = d0 + ty + r * 8;
        dst[(size_t)d * SEQ + s0 + tx] = t[tx][ty + r * 8];
    }
}

// ============================ GEMM body (proj & out): cp.async 3-stage ============================
#define P_ST 80
#define P_ARR 10240
#define P_BUF (3 * P_ARR)

template <typename EPI>
__device__ __forceinline__ void gemm128_body(const __half* Xh, const __half* Xl,
                                             const __half* Bt, char* sm, EPI epi) {
    const int tid = threadIdx.x, lane = tid & 31, wid = tid >> 5;
    const int wm = wid >> 1, wn = wid & 1;
    float acc[2][8][4] = {};

    const int r0 = tid >> 2, c0 = (tid & 3) * 16;
    const int r1 = (tid + 256) >> 2, c1 = ((tid + 256) & 3) * 16;

    auto issue = [&](int c) {
        char* base = sm + (c % 3) * P_BUF;
        uint32_t Ah = sptr(base), Al = Ah + P_ARR, Bh = Al + P_ARR;
        int k0 = c * 32;
        cp16(Ah + r0 * P_ST + c0, Xh + (size_t)r0 * DIM + k0 + c0 / 2);
        cp16(Ah + r1 * P_ST + c1, Xh + (size_t)r1 * DIM + k0 + c1 / 2);
        cp16(Al + r0 * P_ST + c0, Xl + (size_t)r0 * DIM + k0 + c0 / 2);
        cp16(Al + r1 * P_ST + c1, Xl + (size_t)r1 * DIM + k0 + c1 / 2);
        cp16(Bh + r0 * P_ST + c0, Bt + (size_t)r0 * DIM + k0 + c0 / 2);
        cp16(Bh + r1 * P_ST + c1, Bt + (size_t)r1 * DIM + k0 + c1 / 2);
        cp_commit();
    };
    issue(0); issue(1);
    for (int c = 0; c < 32; c++) {
        if (c < 31) cp_wait1(); else cp_wait0();
        __syncthreads();
        char* base = sm + (c % 3) * P_BUF;
        mma_block<P_ST, 2, 8>(base, base + P_ARR, base + 2 * P_ARR,
                              wm, wn, lane, acc);
        if (c + 2 < 32) issue(c + 2);
    }
    epi(acc, wm, wn, lane);
}

__global__ void __launch_bounds__(256, 2)
proj_mma(const float* __restrict__ bq, const float* __restrict__ bk,
         const float* __restrict__ bv) {
    extern __shared__ char sm[];
    const int z = blockIdx.z;
    const int bn = blockIdx.x * 128, bm = blockIdx.y * 128;
    const __half* Bt = g_wt + (size_t)z * DIM * DIM + (size_t)bn * DIM;
    const float* bias = (z == 0) ? bq : (z == 1) ? bk : bv;

    gemm128_body(g_xh + (size_t)bm * DIM, g_xl + (size_t)bm * DIM, Bt, sm,
        [&](float (&acc)[2][8][4], int wm, int wn, int lane) {
#pragma unroll
            for (int mt = 0; mt < 2; mt++) {
#pragma unroll
                for (int nt = 0; nt < 8; nt++) {
                    int n = bn + 64 * wn + 8 * nt + 2 * (lane & 3);
                    float bx = bias[n], by = bias[n + 1];
                    int h = n >> 6, dh = n & 63;
                    int m0 = bm + 32 * wm + 16 * mt + (lane >> 2);
#pragma unroll
                    for (int half = 0; half < 2; half++) {
                        int m = m0 + 8 * half;
                        int b = m >> 11, s = m & 2047;
                        float va = acc[mt][nt][2 * half + 0] + bx;
                        float vb = acc[mt][nt][2 * half + 1] + by;
                        size_t off = ((size_t)(b * NH + h) * SEQ + s) * DH + dh;
                        __half ha = __float2half(va);
                        __half hb = __float2half(vb);
                        if (z == 0) {
                            __half la = __float2half(va - __half2float(ha));
                            __half lb = __float2half(vb - __half2float(hb));
                            *(__half2*)(g_qh + off) = __halves2half2(ha, hb);
                            *(__half2*)(g_ql + off) = __halves2half2(la, lb);
                        } else if (z == 1) {
                            *(__half2*)(g_kh + off) = __halves2half2(ha, hb);
                        } else {
                            *(__half2*)(g_vn + off) = __halves2half2(ha, hb);
                        }
                    }
                }
            }
        });
}

__global__ void __launch_bounds__(256, 2)
out_mma(const float* __restrict__ bo, float* __restrict__ out) {
    extern __shared__ char sm[];
    const int bn = blockIdx.x * 128, bm = blockIdx.y * 128;
    const __half* Bt = g_wt + (size_t)3 * DIM * DIM + (size_t)bn * DIM;

    gemm128_body(g_ch + (size_t)bm * DIM, g_cl + (size_t)bm * DIM, Bt, sm,
        [&](float (&acc)[2][8][4], int wm, int wn, int lane) {
#pragma unroll
            for (int mt = 0; mt < 2; mt++) {
#pragma unroll
                for (int nt = 0; nt < 8; nt++) {
                    int n = bn + 64 * wn + 8 * nt + 2 * (lane & 3);
                    float bx = bo[n], by = bo[n + 1];
                    int m0 = bm + 32 * wm + 16 * mt + (lane >> 2);
#pragma unroll
                    for (int half = 0; half < 2; half++) {
                        int m = m0 + 8 * half;
                        float2 o;
                        o.x = acc[mt][nt][2 * half + 0] + bx;
                        o.y = acc[mt][nt][2 * half + 1] + by;
                        *(float2*)(out + (size_t)m * DIM + n) = o;
                    }
                }
            }
        });
}

// ============================ flash (FA-2, R15 version) ============================
#define F_ST 144
#define F_ARR 9216            // 64 x 144
#define F_SMEM (6 * F_ARR)    // 55296

__global__ void __launch_bounds__(128, 4)
flash_mma() {
    extern __shared__ char sm[];
    const int tid = threadIdx.x, lane = tid & 31, wid = tid >> 5;
    const int tid2 = lane & 3;
    const int bh = blockIdx.y;
    const int b = bh >> 4, h = bh & 15;
    const int qt = blockIdx.x * 64;
    const uint32_t sb = sptr(sm);
    const int row0 = wid * 16 + (lane >> 2);   // local q-row
    const int row1 = row0 + 8;

    auto issueKV = [&](int t) {
        int buf = t & 1;
        int kt = t * 64;
#pragma unroll
        for (int it = 0; it < 4; it++) {
            int idx = it * 128 + tid;
            int row = idx >> 3, c = idx & 7;
            cp16(sb + 2 * F_ARR + buf * F_ARR + row * F_ST + c * 16,
                 g_kh + ((size_t)bh * SEQ + kt + row) * DH + c * 8);
            cp16(sb + 4 * F_ARR + buf * F_ARR + row * F_ST + c * 16,
                 g_vT + ((size_t)bh * DH + row) * SEQ + kt + c * 8);
        }
        cp_commit();
    };
    {
#pragma unroll
        for (int it = 0; it < 4; it++) {
            int idx = it * 128 + tid;
            int row = idx >> 3, c = idx & 7;
            size_t src = ((size_t)bh * SEQ + qt + row) * DH + c * 8;
            cp16(sb + row * F_ST + c * 16, g_qh + src);
            cp16(sb + F_ARR + row * F_ST + c * 16, g_ql + src);
        }
        issueKV(0);
        issueKV(1);
    }

    float M0 = -1e30f, M1 = -1e30f, Z0 = 0.f, Z1 = 0.f;
    float acc_c[8][4] = {};

    for (int t = 0; t < 32; t++) {
        const int kt = t * 64;
        const int buf = t & 1;
        if (t < 31) cp_wait1(); else cp_wait0();
        __syncthreads();

        // ---- S = Q @ K^T (2-term A split) ----
        float acc_s[8][4] = {};
        const uint32_t kbase = sb + 2 * F_ARR + buf * F_ARR;
#pragma unroll
        for (int ks = 0; ks < 4; ks++) {
            uint32_t ah[4], al[4];
            uint32_t aoff = (uint32_t)(wid * 16 + (lane & 15)) * F_ST +
                            ((lane >> 4) * 16) + ks * 32;
            ldm_x4(ah, sb + aoff);
            ldm_x4(al, sb + F_ARR + aoff);
#pragma unroll
            for (int np = 0; np < 4; np++) {
                uint32_t boff = (uint32_t)(np * 16 + ((lane >> 4) << 3) +
                                           (lane & 7)) * F_ST +
                                (((lane >> 3) & 1) * 16) + ks * 32;
                uint32_t bh4[4];
                ldm_x4(bh4, kbase + boff);
                mma16816(acc_s[2 * np],     ah, bh4);
                mma16816(acc_s[2 * np],     al, bh4);
                mma16816(acc_s[2 * np + 1], ah, bh4 + 2);
                mma16816(acc_s[2 * np + 1], al, bh4 + 2);
            }
        }

        // ---- scale + premasked fp16 add + in-quad row max ----
        const float scale = 0.125f;
        float mx0 = -1e30f, mx1 = -1e30f;
        const __half* mr0 = g_mk + (size_t)(qt + row0) * SEQ + kt;
        const __half* mr1 = g_mk + (size_t)(qt + row1) * SEQ + kt;
#pragma unroll
        for (int nt = 0; nt < 8; nt++) {
            int kc = nt * 8 + tid2 * 2;
            float2 mv0 = __half22float2(*(const __half2*)(mr0 + kc));
            float2 mv1 = __half22float2(*(const __half2*)(mr1 + kc));
            acc_s[nt][0] = acc_s[nt][0] * scale + mv0.x;
            acc_s[nt][1] = acc_s[nt][1] * scale + mv0.y;
            acc_s[nt][2] = acc_s[nt][2] * scale + mv1.x;
            acc_s[nt][3] = acc_s[nt][3] * scale + mv1.y;
            mx0 = fmaxf(mx0, fmaxf(acc_s[nt][0], acc_s[nt][1]));
            mx1 = fmaxf(mx1, fmaxf(acc_s[nt][2], acc_s[nt][3]));
        }
        mx0 = fmaxf(mx0, __shfl_xor_sync(0xffffffffu, mx0, 1));
        mx0 = fmaxf(mx0, __shfl_xor_sync(0xffffffffu, mx0, 2));
        mx1 = fmaxf(mx1, __shfl_xor_sync(0xffffffffu, mx1, 1));
        mx1 = fmaxf(mx1, __shfl_xor_sync(0xffffffffu, mx1, 2));

        float Mn0 = fmaxf(M0, mx0), Mn1 = fmaxf(M1, mx1);
        float f0 = __expf(M0 - Mn0), f1 = __expf(M1 - Mn1);
        float g0 = __expf(mx0 - Mn0), g1 = __expf(mx1 - Mn1);
        M0 = Mn0; M1 = Mn1;
        if (tid2 == 0) {
            g_pm[((size_t)bh * SEQ + qt + row0) * 32 + t] = mx0;
            g_pm[((size_t)bh * SEQ + qt + row1) * 32 + t] = mx1;
        }

        // ---- exp, P~ gmem store, in-register A-frags, partial sums ----
        __half* p0 = g_pt + ((size_t)bh * SEQ + qt + row0) * SEQ + kt;
        __half* p1 = g_pt + ((size_t)bh * SEQ + qt + row1) * SEQ + kt;
        uint32_t fa[8], fb[8];
        float s0 = 0.f, s1 = 0.f;
#pragma unroll
        for (int nt = 0; nt < 8; nt++) {
            int kc = nt * 8 + tid2 * 2;
            float e0 = __expf(acc_s[nt][0] - mx0);
            float e1 = __expf(acc_s[nt][1] - mx0);
            float e2 = __expf(acc_s[nt][2] - mx1);
            float e3 = __expf(acc_s[nt][3] - mx1);
            s0 += e0 + e1;
            s1 += e2 + e3;
            *(__half2*)(p0 + kc) = __floats2half2_rn(e0, e1);
            *(__half2*)(p1 + kc) = __floats2half2_rn(e2, e3);
            __half2 a2 = __floats2half2_rn(e0 * g0, e1 * g0);
            __half2 b2 = __floats2half2_rn(e2 * g1, e3 * g1);
            fa[nt] = *(uint32_t*)&a2;
            fb[nt] = *(uint32_t*)&b2;
        }
        s0 += __shfl_xor_sync(0xffffffffu, s0, 1);
        s0 += __shfl_xor_sync(0xffffffffu, s0, 2);
        s1 += __shfl_xor_sync(0xffffffffu, s1, 1);
        s1 += __shfl_xor_sync(0xffffffffu, s1, 2);
        Z0 = Z0 * f0 + s0 * g0;
        Z1 = Z1 * f1 + s1 * g1;

        // ---- rescale running ctx ----
#pragma unroll
        for (int nt = 0; nt < 8; nt++) {
            acc_c[nt][0] *= f0; acc_c[nt][1] *= f0;
            acc_c[nt][2] *= f1; acc_c[nt][3] *= f1;
        }

        // ---- ctx += P @ V^T (A-frags straight from registers) ----
        const uint32_t vbase = sb + 4 * F_ARR + buf * F_ARR;
#pragma unroll
        for (int ks = 0; ks < 4; ks++) {
            uint32_t a[4] = { fa[2 * ks], fb[2 * ks],
                              fa[2 * ks + 1], fb[2 * ks + 1] };
#pragma unroll
            for (int np = 0; np < 4; np++) {
                uint32_t boff = (uint32_t)(np * 16 + ((lane >> 4) << 3) +
                                           (lane & 7)) * F_ST +
                                (((lane >> 3) & 1) * 16) + ks * 32;
                uint32_t bv4[4];
                ldm_x4(bv4, vbase + boff);
                mma16816(acc_c[2 * np],     a, bv4);
                mma16816(acc_c[2 * np + 1], a, bv4 + 2);
            }
        }
        __syncthreads();
        if (t + 2 < 32) issueKV(t + 2);
    }

    // ---- epilogue ----
    if (tid2 == 0) {
        g_rowC[(size_t)bh * SEQ + qt + row0] = M0 + __logf(Z0);
        g_rowC[(size_t)bh * SEQ + qt + row1] = M1 + __logf(Z1);
    }
    float i0 = 1.0f / Z0, i1 = 1.0f / Z1;
    size_t o0 = ((size_t)b * SEQ + qt + row0) * DIM + h * DH;
    size_t o1 = ((size_t)b * SEQ + qt + row1) * DIM + h * DH;
#pragma unroll
    for (int nt = 0; nt < 8; nt++) {
        int nl = nt * 8 + tid2 * 2;
        float va = acc_c[nt][0] * i0, vb = acc_c[nt][1] * i0;
        float vc = acc_c[nt][2] * i1, vd = acc_c[nt][3] * i1;
        __half ha = __float2half(va), hb = __float2half(vb);
        __half hc = __float2half(vc), hd = __float2half(vd);
        *(__half2*)(g_ch + o0 + nl) = __halves2half2(ha, hb);
        *(__half2*)(g_cl + o0 + nl) =
            __halves2half2(__float2half(va - __half2float(ha)),
                           __float2half(vb - __half2float(hb)));
        *(__half2*)(g_ch + o1 + nl) = __halves2half2(hc, hd);
        *(__half2*)(g_cl + o1 + nl) =
            __halves2half2(__float2half(vc - __half2float(hc)),
                           __float2half(vd - __half2float(hd)));
    }
}

// ============================ normalize: attn = P~ * exp(m_t - C) ============================
__global__ void __launch_bounds__(256)
normalize_attn(float* __restrict__ attn) {
    const size_t row = blockIdx.x;           // bh*SEQ + qrow
    const int tid = threadIdx.x;
    const __half* p = g_pt + row * SEQ;
    float* a = attn + row * SEQ;
    const float C = g_rowC[row];
    const int e0 = tid * 8;
    const float sc = __expf(g_pm[row * 32 + (e0 >> 6)] - C);
    uint4 raw = *(const uint4*)(p + e0);
    const __half2* hp = (const __half2*)&raw;
    float2 f0 = __half22float2(hp[0]);
    float2 f1 = __half22float2(hp[1]);
    float2 f2 = __half22float2(hp[2]);
    float2 f3 = __half22float2(hp[3]);
    stcs4(a + e0,     make_float4(f0.x * sc, f0.y * sc, f1.x * sc, f1.y * sc));
    stcs4(a + e0 + 4, make_float4(f2.x * sc, f2.y * sc, f3.x * sc, f3.y * sc));
}

// ============================ launcher (graph-forked streams) ============================
extern "C" void kernel_launch(void* const* d_in, const int* in_sizes, int n_in,
                              void* d_out, int out_size) {
    const float* x    = (const float*)d_in[0];
    const float* mask = (const float*)d_in[1];
    const float* Wq   = (const float*)d_in[2];
    const float* bq   = (const float*)d_in[3];
    const float* Wk   = (const float*)d_in[4];
    const float* bk   = (const float*)d_in[5];
    const float* Wv   = (const float*)d_in[6];
    const float* bv   = (const float*)d_in[7];
    const float* Wo   = (const float*)d_in[8];
    const float* bo   = (const float*)d_in[9];

    float* out  = (float*)d_out;                 // [B,S,D]
    float* attn = out + (size_t)BS * DIM;        // [B,H,S,S]

    const int projSmem = 3 * P_BUF;              // 92160
    cudaFuncSetAttribute(proj_mma,  cudaFuncAttributeMaxDynamicSharedMemorySize, projSmem);
    cudaFuncSetAttribute(flash_mma, cudaFuncAttributeMaxDynamicSharedMemorySize, F_SMEM);
    cudaFuncSetAttribute(out_mma,   cudaFuncAttributeMaxDynamicSharedMemorySize, projSmem);

    // side stream + events for parallel graph branches (host objects; not
    // device memory). Created per call; not destroyed mid-capture.
    cudaStream_t s1;
    cudaStreamCreateWithFlags(&s1, cudaStreamNonBlocking);
    cudaEvent_t evRoot, evMask, evFlash, evNorm;
    cudaEventCreateWithFlags(&evRoot,  cudaEventDisableTiming);
    cudaEventCreateWithFlags(&evMask,  cudaEventDisableTiming);
    cudaEventCreateWithFlags(&evFlash, cudaEventDisableTiming);
    cudaEventCreateWithFlags(&evNorm,  cudaEventDisableTiming);

    // branch: pack_mask runs concurrently with x/W prep + proj
    cudaEventRecord(evRoot, 0);
    cudaStreamWaitEvent(s1, evRoot, 0);
    pack_mask<<<(size_t)SEQ * SEQ / 1024, 256, 0, s1>>>(mask);
    cudaEventRecord(evMask, s1);

    split_x<<<BS * DIM / 1024, 256>>>(x);
    transpose_pack_w<<<dim3(32, 32, 4), dim3(32, 8)>>>(Wq, Wk, Wv, Wo);
    proj_mma<<<dim3(8, 32, 3), 256, projSmem>>>(bq, bk, bv);
    transpose_v<<<dim3(64, 2, 32), dim3(32, 8)>>>();
    cudaStreamWaitEvent(0, evMask, 0);           // flash needs g_mk
    flash_mma<<<dim3(32, 32), 128, F_SMEM>>>();

    // branch: normalize_attn runs concurrently with out_mma
    cudaEventRecord(evFlash, 0);
    cudaStreamWaitEvent(s1, evFlash, 0);
    normalize_attn<<<NBH * SEQ, 256, 0, s1>>>(attn);
    cudaEventRecord(evNorm, s1);

    out_mma<<<dim3(8, 32), 256, projSmem>>>(bo, out);
    cudaStreamWaitEvent(0, evNorm, 0);           // join before returning
}